// round 13
// baseline (speedup 1.0000x reference)
#include <cuda_runtime.h>
#include <cuda_fp16.h>
#include <math.h>
#include <stdint.h>

// ---------------- problem constants ----------------
#define BATCH 2
#define SEQ   2048
#define DM    1024
#define NH    16
#define DH    64
#define NTOK  (BATCH*SEQ)        // 4096
#define CHUNK 128
#define NCH   (SEQ/CHUNK)        // 16
#define NBH   (BATCH*NH)         // 32

// ---------------- scratch (device globals; no allocs allowed) ----------------
__device__ __half  g_xnorm_h[NTOK*DM];
__device__ __half  g_xr_h   [NTOK*DM];
__device__ __half  g_qkv_h  [NTOK*3*DM];
__device__ __half  g_gate_h [NTOK*DM];
__device__ __half  g_qh_h   [NBH*SEQ*DH];
__device__ __half  g_kh_h   [NBH*SEQ*DH];
__device__ __half  g_vh_h   [NBH*SEQ*DH];
__device__ float   g_kv     [NBH*NCH*DH*DH];
__device__ float   g_kvpre  [NBH*NCH*DH*DH];
__device__ float   g_ksum   [NBH*NCH*DH];
__device__ float   g_kspre  [NBH*NCH*DH];
__device__ __half  g_ctx_h  [NTOK*DM];
__device__ __half  g_wqkv_h [(3*DM)*DM];   // [n][k] fp16 (transposed)
__device__ __half  g_wgate_h[DM*DM];       // [n][k]
__device__ __half  g_wproj_h[DM*DM];       // [n][k]

// ---------------- helpers ----------------
__device__ __forceinline__ void mma_f16(float* c, const uint32_t* a, const uint32_t* b) {
    asm volatile(
        "mma.sync.aligned.m16n8k16.row.col.f32.f16.f16.f32 "
        "{%0,%1,%2,%3}, {%4,%5,%6,%7}, {%8,%9}, {%0,%1,%2,%3};"
        : "+f"(c[0]), "+f"(c[1]), "+f"(c[2]), "+f"(c[3])
        : "r"(a[0]), "r"(a[1]), "r"(a[2]), "r"(a[3]), "r"(b[0]), "r"(b[1]));
}
__device__ __forceinline__ void ldsm_x4(uint32_t* r, uint32_t addr) {
    asm volatile("ldmatrix.sync.aligned.m8n8.x4.shared.b16 {%0,%1,%2,%3}, [%4];"
        : "=r"(r[0]), "=r"(r[1]), "=r"(r[2]), "=r"(r[3]) : "r"(addr));
}
__device__ __forceinline__ void ldsm_x2(uint32_t* r, uint32_t addr) {
    asm volatile("ldmatrix.sync.aligned.m8n8.x2.shared.b16 {%0,%1}, [%2];"
        : "=r"(r[0]), "=r"(r[1]) : "r"(addr));
}
__device__ __forceinline__ uint32_t smem_u32(const void* p) {
    uint32_t a;
    asm("{ .reg .u64 t; cvta.to.shared.u64 t, %1; cvt.u32.u64 %0, t; }" : "=r"(a) : "l"(p));
    return a;
}
__device__ __forceinline__ void cp16(uint32_t dst, const void* src) {
    asm volatile("cp.async.cg.shared.global [%0], [%1], 16;" :: "r"(dst), "l"(src));
}
#define CP_COMMIT() asm volatile("cp.async.commit_group;" ::: "memory")
#define CP_WAIT(n)  asm volatile("cp.async.wait_group %0;" :: "n"(n) : "memory")

// ================= fp16 mma.sync GEMM core (templated M rows) =================
// CTA tile (MFRAG*32)x128, BK=32, 128 threads (4 warps 2x2), warp tile (MFRAG*16)x64.
#define ROW_H 40
#define ASTB (128*ROW_H*2)       // stage stride sized for 128 rows (half tiles fill less)
#define BSTB (128*ROW_H*2)
#define GEMM_SMEM_BYTES (3*(ASTB+BSTB))  // 61440
#define NKT (DM/32)

template<int MFRAG, bool SIGMOID, bool HALF_OUT>
__device__ __forceinline__ void gemm_tile(
    const __half* __restrict__ A, const __half* __restrict__ B,
    const float* __restrict__ bias, void* __restrict__ Cv,
    int N, int bm0, int bn0, char* sm) {

    uint32_t sA = smem_u32(sm);
    uint32_t sB = sA + 3 * ASTB;
    int tid = threadIdx.x;
    int wid = tid >> 5, lane = tid & 31;
    int gid = lane >> 2, tig = lane & 3;
    int wm = (wid & 1) * (MFRAG * 16), wn = (wid >> 1) * 64;

    float c[MFRAG][8][4];
    #pragma unroll
    for (int mf = 0; mf < MFRAG; mf++)
        #pragma unroll
        for (int nf = 0; nf < 8; nf++)
            #pragma unroll
            for (int r = 0; r < 4; r++) c[mf][nf][r] = 0.f;

    auto stage = [&](int s, int kt) {
        const __half* Ab = A + (size_t)bm0 * DM + kt * 32;
        const __half* Bb = B + (size_t)bn0 * DM + kt * 32;
        uint32_t sAb = sA + s * ASTB;
        uint32_t sBb = sB + s * BSTB;
        #pragma unroll
        for (int l = 0; l < MFRAG; l++) {          // A: MFRAG*32 rows
            int id = tid + l * 128;
            int r  = id >> 2;
            cp16(sAb + r * (ROW_H * 2) + (id & 3) * 16, Ab + (size_t)r * DM + (id & 3) * 8);
        }
        #pragma unroll
        for (int l = 0; l < 4; l++) {              // B: 128 rows
            int id = tid + l * 128;
            int r  = id >> 2;
            cp16(sBb + r * (ROW_H * 2) + (id & 3) * 16, Bb + (size_t)r * DM + (id & 3) * 8);
        }
    };

    uint32_t aOff = (uint32_t)(((wm + (lane & 15)) * ROW_H + (lane >> 4) * 8) * 2);
    uint32_t bOff = (uint32_t)(((wn + (lane & 7)) * ROW_H + ((lane >> 3) & 1) * 8) * 2);

    stage(0, 0); CP_COMMIT();
    stage(1, 1); CP_COMMIT();

    for (int kt = 0; kt < NKT; kt++) {
        if (kt + 1 < NKT) { CP_WAIT(1); } else { CP_WAIT(0); }
        __syncthreads();

        int buf = kt % 3;
        uint32_t aBase = sA + buf * ASTB + aOff;
        uint32_t bBase = sB + buf * BSTB + bOff;
        #pragma unroll
        for (int ks = 0; ks < 2; ks++) {
            uint32_t a[MFRAG][4], b[8][2];
            #pragma unroll
            for (int mf = 0; mf < MFRAG; mf++)
                ldsm_x4(a[mf], aBase + (mf * 16 * ROW_H + ks * 16) * 2);
            #pragma unroll
            for (int nf = 0; nf < 8; nf++)
                ldsm_x2(b[nf], bBase + (nf * 8 * ROW_H + ks * 16) * 2);
            #pragma unroll
            for (int mf = 0; mf < MFRAG; mf++)
                #pragma unroll
                for (int nf = 0; nf < 8; nf++)
                    mma_f16(c[mf][nf], a[mf], b[nf]);
        }

        if (kt + 2 < NKT) { stage((kt + 2) % 3, kt + 2); CP_COMMIT(); }
    }

    // epilogue
    #pragma unroll
    for (int mf = 0; mf < MFRAG; mf++) {
        int row = bm0 + wm + mf * 16 + gid;
        #pragma unroll
        for (int nf = 0; nf < 8; nf++) {
            int col = bn0 + wn + nf * 8 + tig * 2;
            float b0 = bias[col], b1 = bias[col + 1];
            float2 o0 = make_float2(c[mf][nf][0] + b0, c[mf][nf][1] + b1);
            float2 o1 = make_float2(c[mf][nf][2] + b0, c[mf][nf][3] + b1);
            if (SIGMOID) {
                o0.x = 1.f / (1.f + expf(-o0.x)); o0.y = 1.f / (1.f + expf(-o0.y));
                o1.x = 1.f / (1.f + expf(-o1.x)); o1.y = 1.f / (1.f + expf(-o1.y));
            }
            if (HALF_OUT) {
                __half* C = (__half*)Cv;
                *(__half2*)(C + (size_t)row * N + col)       = __floats2half2_rn(o0.x, o0.y);
                *(__half2*)(C + (size_t)(row + 8) * N + col) = __floats2half2_rn(o1.x, o1.y);
            } else {
                float* C = (float*)Cv;
                *(float2*)(C + (size_t)row * N + col) = o0;
                *(float2*)(C + (size_t)(row + 8) * N + col) = o1;
            }
        }
    }
}

// persistent dual-job GEMM with tail splitting:
//   items 0..767   : qkv full tiles (128x128)
//   items 768..887 : gate full tiles 0..119
//   items 888..1159: gate HALF tiles (64x128) covering gate tiles 120..255
#define QKV_TILES 768
#define FULL_ITEMS 888
#define ALL_ITEMS 1160

__global__ void __launch_bounds__(128, 2)
mma_gemm_dual(const __half* __restrict__ Aq, const __half* __restrict__ Bq,
              const float* __restrict__ biasq,
              const __half* __restrict__ Ag, const __half* __restrict__ Bg,
              const float* __restrict__ biasg) {
    extern __shared__ char smc[];
    for (int it = blockIdx.x; it < ALL_ITEMS; it += gridDim.x) {
        __syncthreads();
        if (it < QKV_TILES) {
            int bm = it / 24, bn = it % 24;
            gemm_tile<4, false, true>(Aq, Bq, biasq, g_qkv_h, 3 * DM, bm * 128, bn * 128, smc);
        } else if (it < FULL_ITEMS) {
            int t2 = it - QKV_TILES;               // 0..119
            int bm = t2 / 8, bn = t2 % 8;
            gemm_tile<4, true, true>(Ag, Bg, biasg, g_gate_h, DM, bm * 128, bn * 128, smc);
        } else {
            int ht = it - FULL_ITEMS;              // 0..271
            int t2 = 120 + (ht >> 1);              // gate tile 120..255
            int bm = t2 / 8, bn = t2 % 8;
            int bm0 = bm * 128 + (ht & 1) * 64;
            gemm_tile<2, true, true>(Ag, Bg, biasg, g_gate_h, DM, bm0, bn * 128, smc);
        }
    }
}

__global__ void __launch_bounds__(128, 2)
mma_gemm_single(const __half* __restrict__ A, const __half* __restrict__ B,
                const float* __restrict__ bias, float* __restrict__ C) {
    extern __shared__ char smc[];
    gemm_tile<4, false, false>(A, B, bias, C, DM, blockIdx.y * 128, blockIdx.x * 128, smc);
}

// ---------------- weight transpose (single launch): fp32 [K][N] -> fp16 [N][K] ----------------
__global__ void transpose_all_kernel(const float* __restrict__ wq, const float* __restrict__ wg,
                                     const float* __restrict__ wp) {
    __shared__ float t[32][33];
    int bxg = blockIdx.x;                   // 0..159: 96 qkv | 32 gate | 32 proj
    const float* W; __half* WT; int N, bx;
    if (bxg < 96)      { W = wq; WT = g_wqkv_h;  N = 3 * DM; bx = bxg * 32; }
    else if (bxg < 128){ W = wg; WT = g_wgate_h; N = DM;     bx = (bxg - 96) * 32; }
    else               { W = wp; WT = g_wproj_h; N = DM;     bx = (bxg - 128) * 32; }
    int by = blockIdx.y * 32;
    int x = threadIdx.x, y = threadIdx.y;   // 32 x 8
    #pragma unroll
    for (int i = 0; i < 32; i += 8)
        t[y + i][x] = W[(size_t)(by + y + i) * N + bx + x];
    __syncthreads();
    #pragma unroll
    for (int i = 0; i < 32; i += 8)
        WT[(size_t)(bx + y + i) * DM + by + x] = __float2half(t[x][y + i]);
}

// ---------------- LayerNorm: fp16 xnorm + fp16 x copy ----------------
__global__ void ln_kernel(const float* __restrict__ x, const float* __restrict__ g,
                          const float* __restrict__ bta) {
    __shared__ float red0[8], red1[8];
    int row = blockIdx.x, tid = threadIdx.x;
    const float* xrp = x + (size_t)row * DM;
    float4 xv = *(const float4*)(xrp + tid * 4);
    float s  = xv.x + xv.y + xv.z + xv.w;
    float s2 = xv.x*xv.x + xv.y*xv.y + xv.z*xv.z + xv.w*xv.w;
    #pragma unroll
    for (int o = 16; o > 0; o >>= 1) {
        s  += __shfl_xor_sync(0xffffffffu, s,  o);
        s2 += __shfl_xor_sync(0xffffffffu, s2, o);
    }
    int w = tid >> 5;
    if ((tid & 31) == 0) { red0[w] = s; red1[w] = s2; }
    __syncthreads();
    if (tid < 32) {
        s  = (tid < 8) ? red0[tid] : 0.f;
        s2 = (tid < 8) ? red1[tid] : 0.f;
        #pragma unroll
        for (int o = 4; o > 0; o >>= 1) {
            s  += __shfl_xor_sync(0xffffffffu, s,  o);
            s2 += __shfl_xor_sync(0xffffffffu, s2, o);
        }
        if (tid == 0) { red0[0] = s; red1[0] = s2; }
    }
    __syncthreads();
    float mu   = red0[0] * (1.f / DM);
    float var  = red1[0] * (1.f / DM) - mu * mu;
    float rstd = rsqrtf(var + 1e-5f);
    float4 gv = *(const float4*)(g + tid * 4);
    float4 bv = *(const float4*)(bta + tid * 4);
    __half2* xn2 = (__half2*)(g_xnorm_h + (size_t)row * DM) + tid * 2;
    __half2* xr2 = (__half2*)(g_xr_h    + (size_t)row * DM) + tid * 2;
    xn2[0] = __floats2half2_rn((xv.x - mu) * rstd * gv.x + bv.x,
                               (xv.y - mu) * rstd * gv.y + bv.y);
    xn2[1] = __floats2half2_rn((xv.z - mu) * rstd * gv.z + bv.z,
                               (xv.w - mu) * rstd * gv.w + bv.w);
    xr2[0] = __floats2half2_rn(xv.x, xv.y);
    xr2[1] = __floats2half2_rn(xv.z, xv.w);
}

// ---------------- fused gate-normalize + head split + elu+1 (fp16 in/out) ----------------
__global__ void gatesplit_kernel() {
    __shared__ float red[8];
    int n = blockIdx.x, tid = threadIdx.x;
    const __half2* g2 = (const __half2*)(g_gate_h + (size_t)n * DM);
    float2 g0 = __half22float2(g2[tid * 2]);
    float2 g1 = __half22float2(g2[tid * 2 + 1]);
    float s = g0.x + g0.y + g1.x + g1.y;
    #pragma unroll
    for (int o = 16; o > 0; o >>= 1) s += __shfl_xor_sync(0xffffffffu, s, o);
    if ((tid & 31) == 0) red[tid >> 5] = s;
    __syncthreads();
    if (tid < 32) {
        s = (tid < 8) ? red[tid] : 0.f;
        #pragma unroll
        for (int o = 4; o > 0; o >>= 1) s += __shfl_xor_sync(0xffffffffu, s, o);
        if (tid == 0) red[0] = s;
    }
    __syncthreads();
    float scale = 1.f / (red[0] * (1.f / DM) + 1e-5f);

    int cix = tid * 4;
    int h = cix >> 6, e = cix & 63;
    int b = n >> 11, t = n & 2047;
    const __half2* qkv2 = (const __half2*)(g_qkv_h + (size_t)n * 3072);
    float2 q0 = __half22float2(qkv2[tid * 2]);
    float2 q1 = __half22float2(qkv2[tid * 2 + 1]);
    float2 k0 = __half22float2(qkv2[512 + tid * 2]);
    float2 k1 = __half22float2(qkv2[512 + tid * 2 + 1]);
    float2 v0 = __half22float2(qkv2[1024 + tid * 2]);
    float2 v1 = __half22float2(qkv2[1024 + tid * 2 + 1]);
    float gn0 = g0.x * scale, gn1 = g0.y * scale, gn2 = g1.x * scale, gn3 = g1.y * scale;
    q0.x *= gn0; q0.y *= gn1; q1.x *= gn2; q1.y *= gn3;
    k0.x *= gn0; k0.y *= gn1; k1.x *= gn2; k1.y *= gn3;
    q0.x = (q0.x > 0.f) ? q0.x + 1.f : expf(q0.x);
    q0.y = (q0.y > 0.f) ? q0.y + 1.f : expf(q0.y);
    q1.x = (q1.x > 0.f) ? q1.x + 1.f : expf(q1.x);
    q1.y = (q1.y > 0.f) ? q1.y + 1.f : expf(q1.y);
    k0.x = (k0.x > 0.f) ? k0.x + 1.f : expf(k0.x);
    k0.y = (k0.y > 0.f) ? k0.y + 1.f : expf(k0.y);
    k1.x = (k1.x > 0.f) ? k1.x + 1.f : expf(k1.x);
    k1.y = (k1.y > 0.f) ? k1.y + 1.f : expf(k1.y);
    size_t o = ((size_t)(b * NH + h) * SEQ + t) * DH + e;
    *(__half2*)(g_qh_h + o)     = __floats2half2_rn(q0.x, q0.y);
    *(__half2*)(g_qh_h + o + 2) = __floats2half2_rn(q1.x, q1.y);
    *(__half2*)(g_kh_h + o)     = __floats2half2_rn(k0.x, k0.y);
    *(__half2*)(g_kh_h + o + 2) = __floats2half2_rn(k1.x, k1.y);
    *(__half2*)(g_vh_h + o)     = __floats2half2_rn(v0.x, v0.y);
    *(__half2*)(g_vh_h + o + 2) = __floats2half2_rn(v1.x, v1.y);
}

// ---------------- pass A: per-chunk KV = k^T@v, ksum (fp16 inputs) ----------------
__global__ void passA_kernel() {
    __shared__ float ks[64][64];
    __shared__ float vs[64][64];
    int blk = blockIdx.x;
    int bh = blk / NCH, c = blk % NCH;
    const __half* kb = g_kh_h + ((size_t)bh * SEQ + c * CHUNK) * DH;
    const __half* vb = g_vh_h + ((size_t)bh * SEQ + c * CHUNK) * DH;
    int tid = threadIdx.x;
    int d = tid & 63, mg = tid >> 6;
    float acc[16];
    #pragma unroll
    for (int i = 0; i < 16; i++) acc[i] = 0.f;
    float ksum = 0.f;
    for (int half = 0; half < 2; half++) {
        __syncthreads();
        #pragma unroll
        for (int l = 0; l < 4; l++) {
            int id = tid + l * 256;
            int r = id >> 4, c4 = (id & 15) * 4;
            const __half2* ksrc = (const __half2*)(kb + half * 4096 + r * 64 + c4);
            const __half2* vsrc = (const __half2*)(vb + half * 4096 + r * 64 + c4);
            float2 ka = __half22float2(ksrc[0]), kb2 = __half22float2(ksrc[1]);
            float2 va = __half22float2(vsrc[0]), vb2 = __half22float2(vsrc[1]);
            *(float4*)&ks[r][c4] = make_float4(ka.x, ka.y, kb2.x, kb2.y);
            *(float4*)&vs[r][c4] = make_float4(va.x, va.y, vb2.x, vb2.y);
        }
        __syncthreads();
        #pragma unroll 4
        for (int t = 0; t < 64; t++) {
            float kd = ks[t][d];
            if (mg == 0) ksum += kd;
            #pragma unroll
            for (int i = 0; i < 16; i++) acc[i] += kd * vs[t][mg * 16 + i];
        }
    }
    float* kvo = g_kv + (size_t)blk * (DH * DH);
    #pragma unroll
    for (int i = 0; i < 16; i += 4)
        *(float4*)(kvo + d * 64 + mg * 16 + i) = make_float4(acc[i], acc[i+1], acc[i+2], acc[i+3]);
    if (mg == 0) g_ksum[blk * DH + d] = ksum;
}

// ---------------- pass B: exclusive prefix over chunks ----------------
__global__ void passB_kernel() {
    int bh = blockIdx.y;
    int e = blockIdx.x * 256 + threadIdx.x;
    float run = 0.f;
    #pragma unroll
    for (int c = 0; c < NCH; c++) {
        size_t idx = ((size_t)bh * NCH + c) * (DH * DH) + e;
        g_kvpre[idx] = run;
        run += g_kv[idx];
    }
    if (blockIdx.x == 0 && threadIdx.x < DH) {
        float r2 = 0.f;
        #pragma unroll
        for (int c = 0; c < NCH; c++) {
            size_t idx = ((size_t)bh * NCH + c) * DH + threadIdx.x;
            g_kspre[idx] = r2;
            r2 += g_ksum[idx];
        }
    }
}

// ---------------- pass C (fp16 q/k/v inputs, fp16 ctx output) ----------------
__global__ void passC_kernel() {
    extern __shared__ float smf[];
    float (*k_sm)[64] = (float(*)[64])smf;
    float (*v_sm)[64] = (float(*)[64])(smf + 128 * 64);
    float (*s_sm)[64] = (float(*)[64])(smf + 2 * 128 * 64);
    float* kp_sm = smf + 2 * 128 * 64 + 64 * 64;

    int blk = blockIdx.x;
    int bh = blk / NCH, c = blk % NCH;
    int b = bh / NH, h = bh % NH;
    int tid = threadIdx.x;
    const __half* qb = g_qh_h + ((size_t)bh * SEQ + c * CHUNK) * DH;
    const __half* kb = g_kh_h + ((size_t)bh * SEQ + c * CHUNK) * DH;
    const __half* vb = g_vh_h + ((size_t)bh * SEQ + c * CHUNK) * DH;

    #pragma unroll
    for (int l = 0; l < 8; l++) {
        int id = tid + l * 256;
        int r = id >> 4, c4 = (id & 15) * 4;
        const __half2* ksrc = (const __half2*)(kb + r * 64 + c4);
        const __half2* vsrc = (const __half2*)(vb + r * 64 + c4);
        float2 ka = __half22float2(ksrc[0]), kb2 = __half22float2(ksrc[1]);
        float2 va = __half22float2(vsrc[0]), vb2 = __half22float2(vsrc[1]);
        *(float4*)&k_sm[r][c4] = make_float4(ka.x, ka.y, kb2.x, kb2.y);
        *(float4*)&v_sm[r][c4] = make_float4(va.x, va.y, vb2.x, vb2.y);
    }
    #pragma unroll
    for (int l = 0; l < 4; l++) {
        int id = tid + l * 256;
        int r = id >> 4, c4 = (id & 15) * 4;
        *(float4*)&s_sm[r][c4] = *(const float4*)(g_kvpre + (size_t)blk * 4096 + r * 64 + c4);
    }
    if (tid < 64) kp_sm[tid] = g_kspre[(size_t)blk * 64 + tid];
    __syncthreads();

    int t = tid >> 1, half = tid & 1;
    float q[64];
    #pragma unroll
    for (int i = 0; i < 64; i += 4) {
        const __half2* qp = (const __half2*)(qb + t * 64 + i);
        float2 qa = __half22float2(qp[0]), qb2 = __half22float2(qp[1]);
        q[i] = qa.x; q[i+1] = qa.y; q[i+2] = qb2.x; q[i+3] = qb2.y;
    }
    float acc[32];
    #pragma unroll
    for (int i = 0; i < 32; i++) acc[i] = 0.f;
    float den = 0.f;

    #pragma unroll 8
    for (int d = 0; d < 64; d++) {
        float qd = q[d];
        den += qd * kp_sm[d];
        #pragma unroll
        for (int i = 0; i < 32; i++) acc[i] += qd * s_sm[d][half + 2 * i];
    }
    for (int s = 0; s <= t; s++) {
        float a = 0.f;
        #pragma unroll
        for (int d = 0; d < 64; d++) a += q[d] * k_sm[s][d];
        den += a;
        #pragma unroll
        for (int i = 0; i < 32; i++) acc[i] += a * v_sm[s][half + 2 * i];
    }
    float inv = 1.f / (den + 1e-5f);
    int token = b * SEQ + c * CHUNK + t;
    __half* outp = g_ctx_h + (size_t)token * DM + h * DH;
    #pragma unroll
    for (int i = 0; i < 32; i++) outp[half + 2 * i] = __float2half(acc[i] * inv);
}

// ---------------- launch ----------------
extern "C" void kernel_launch(void* const* d_in, const int* in_sizes, int n_in,
                              void* d_out, int out_size) {
    const float* x      = (const float*)d_in[0];
    const float* ln_g   = (const float*)d_in[1];
    const float* ln_b   = (const float*)d_in[2];
    const float* w_qkv  = (const float*)d_in[3];
    const float* b_qkv  = (const float*)d_in[4];
    const float* w_gate = (const float*)d_in[5];
    const float* b_gate = (const float*)d_in[6];
    const float* w_proj = (const float*)d_in[7];
    const float* b_proj = (const float*)d_in[8];
    float* out = (float*)d_out;

    void *p_xnorm, *p_xr, *p_ctx, *p_wqkv, *p_wgate, *p_wproj;
    cudaGetSymbolAddress(&p_xnorm, g_xnorm_h);
    cudaGetSymbolAddress(&p_xr,    g_xr_h);
    cudaGetSymbolAddress(&p_ctx,   g_ctx_h);
    cudaGetSymbolAddress(&p_wqkv,  g_wqkv_h);
    cudaGetSymbolAddress(&p_wgate, g_wgate_h);
    cudaGetSymbolAddress(&p_wproj, g_wproj_h);

    const int smemC = (2 * 128 * 64 + 64 * 64 + 64) * 4;
    cudaFuncSetAttribute(passC_kernel, cudaFuncAttributeMaxDynamicSharedMemorySize, smemC);
    cudaFuncSetAttribute(mma_gemm_dual,   cudaFuncAttributeMaxDynamicSharedMemorySize, GEMM_SMEM_BYTES);
    cudaFuncSetAttribute(mma_gemm_single, cudaFuncAttributeMaxDynamicSharedMemorySize, GEMM_SMEM_BYTES);

    // 0. transpose all weights to fp16 [N][K] (single launch)
    transpose_all_kernel<<<dim3(160, DM / 32), dim3(32, 8)>>>(w_qkv, w_gate, w_proj);
    // 1. LayerNorm (emits fp16 xnorm + fp16 x)
    ln_kernel<<<NTOK, 256>>>(x, ln_g, ln_b);
    // 2+3. persistent dual GEMM with tail-split half tiles
    mma_gemm_dual<<<296, 128, GEMM_SMEM_BYTES>>>(
        (const __half*)p_xnorm, (const __half*)p_wqkv, b_qkv,
        (const __half*)p_xr,    (const __half*)p_wgate, b_gate);
    // 4+5. fused gate-normalize + split + elu+1 (fp16 in/out)
    gatesplit_kernel<<<NTOK, 256>>>();
    // 6-8. chunked causal linear attention (fp16 inputs, fp32 compute)
    passA_kernel<<<NBH * NCH, 256>>>();
    passB_kernel<<<dim3(16, NBH), 256>>>();
    passC_kernel<<<NBH * NCH, 256, smemC>>>();
    // 9. projection (fp32 output)
    mma_gemm_single<<<dim3(DM / 128, NTOK / 128), 128, GEMM_SMEM_BYTES>>>(
        (const __half*)p_ctx, (const __half*)p_wproj, b_proj, out);
}

// round 14
// speedup vs baseline: 1.5908x; 1.5908x over previous
#include <cuda_runtime.h>
#include <cuda_fp16.h>
#include <math.h>
#include <stdint.h>

// ---------------- problem constants ----------------
#define BATCH 2
#define SEQ   2048
#define DM    1024
#define NH    16
#define DH    64
#define NTOK  (BATCH*SEQ)        // 4096
#define CHUNK 128
#define NCH   (SEQ/CHUNK)        // 16
#define NBH   (BATCH*NH)         // 32

// ---------------- scratch (device globals; no allocs allowed) ----------------
__device__ __half  g_xnorm_h[NTOK*DM];
__device__ __half  g_xr_h   [NTOK*DM];
__device__ __half  g_qkv_h  [NTOK*3*DM];
__device__ __half  g_gate_h [NTOK*DM];
__device__ __half  g_qh_h   [NBH*SEQ*DH];
__device__ __half  g_kh_h   [NBH*SEQ*DH];
__device__ __half  g_vh_h   [NBH*SEQ*DH];
__device__ float   g_kv     [NBH*NCH*DH*DH];   // per chunk: [m][d] (TRANSPOSED)
__device__ float   g_kvpre  [NBH*NCH*DH*DH];   // [m][d]
__device__ float   g_ksum   [NBH*NCH*DH];
__device__ float   g_kspre  [NBH*NCH*DH];
__device__ __half  g_ctx_h  [NTOK*DM];
__device__ __half  g_wqkv_h [(3*DM)*DM];   // [n][k] fp16 (transposed)
__device__ __half  g_wgate_h[DM*DM];       // [n][k]
__device__ __half  g_wproj_h[DM*DM];       // [n][k]

// ---------------- helpers ----------------
__device__ __forceinline__ void mma_f16(float* c, const uint32_t* a, const uint32_t* b) {
    asm volatile(
        "mma.sync.aligned.m16n8k16.row.col.f32.f16.f16.f32 "
        "{%0,%1,%2,%3}, {%4,%5,%6,%7}, {%8,%9}, {%0,%1,%2,%3};"
        : "+f"(c[0]), "+f"(c[1]), "+f"(c[2]), "+f"(c[3])
        : "r"(a[0]), "r"(a[1]), "r"(a[2]), "r"(a[3]), "r"(b[0]), "r"(b[1]));
}
__device__ __forceinline__ void ldsm_x4(uint32_t* r, uint32_t addr) {
    asm volatile("ldmatrix.sync.aligned.m8n8.x4.shared.b16 {%0,%1,%2,%3}, [%4];"
        : "=r"(r[0]), "=r"(r[1]), "=r"(r[2]), "=r"(r[3]) : "r"(addr));
}
__device__ __forceinline__ void ldsm_x2(uint32_t* r, uint32_t addr) {
    asm volatile("ldmatrix.sync.aligned.m8n8.x2.shared.b16 {%0,%1}, [%2];"
        : "=r"(r[0]), "=r"(r[1]) : "r"(addr));
}
__device__ __forceinline__ uint32_t smem_u32(const void* p) {
    uint32_t a;
    asm("{ .reg .u64 t; cvta.to.shared.u64 t, %1; cvt.u32.u64 %0, t; }" : "=r"(a) : "l"(p));
    return a;
}
__device__ __forceinline__ void cp16(uint32_t dst, const void* src) {
    asm volatile("cp.async.cg.shared.global [%0], [%1], 16;" :: "r"(dst), "l"(src));
}
#define CP_COMMIT() asm volatile("cp.async.commit_group;" ::: "memory")
#define CP_WAIT(n)  asm volatile("cp.async.wait_group %0;" :: "n"(n) : "memory")

// ================= fp16 mma.sync GEMM core (R12 config) =================
#define ROW_H 40
#define ASTB (128*ROW_H*2)
#define BSTB (128*ROW_H*2)
#define GEMM_SMEM_BYTES (3*(ASTB+BSTB))  // 61440
#define NKT (DM/32)

template<bool SIGMOID, bool HALF_OUT>
__device__ __forceinline__ void gemm_tile(
    const __half* __restrict__ A, const __half* __restrict__ B,
    const float* __restrict__ bias, void* __restrict__ Cv,
    int N, int bm0, int bn0, char* sm) {

    uint32_t sA = smem_u32(sm);
    uint32_t sB = sA + 3 * ASTB;
    int tid = threadIdx.x;
    int wid = tid >> 5, lane = tid & 31;
    int gid = lane >> 2, tig = lane & 3;
    int wm = (wid & 1) * 64, wn = (wid >> 1) * 64;

    float c[4][8][4];
    #pragma unroll
    for (int mf = 0; mf < 4; mf++)
        #pragma unroll
        for (int nf = 0; nf < 8; nf++)
            #pragma unroll
            for (int r = 0; r < 4; r++) c[mf][nf][r] = 0.f;

    auto stage = [&](int s, int kt) {
        const __half* Ab = A + (size_t)bm0 * DM + kt * 32;
        const __half* Bb = B + (size_t)bn0 * DM + kt * 32;
        uint32_t sAb = sA + s * ASTB;
        uint32_t sBb = sB + s * BSTB;
        #pragma unroll
        for (int l = 0; l < 4; l++) {
            int id = tid + l * 128;
            int r  = id >> 2;
            cp16(sAb + r * (ROW_H * 2) + (id & 3) * 16, Ab + (size_t)r * DM + (id & 3) * 8);
            cp16(sBb + r * (ROW_H * 2) + (id & 3) * 16, Bb + (size_t)r * DM + (id & 3) * 8);
        }
    };

    uint32_t aOff = (uint32_t)(((wm + (lane & 15)) * ROW_H + (lane >> 4) * 8) * 2);
    uint32_t bOff = (uint32_t)(((wn + (lane & 7)) * ROW_H + ((lane >> 3) & 1) * 8) * 2);

    stage(0, 0); CP_COMMIT();
    stage(1, 1); CP_COMMIT();

    for (int kt = 0; kt < NKT; kt++) {
        if (kt + 1 < NKT) { CP_WAIT(1); } else { CP_WAIT(0); }
        __syncthreads();

        int buf = kt % 3;
        uint32_t aBase = sA + buf * ASTB + aOff;
        uint32_t bBase = sB + buf * BSTB + bOff;
        #pragma unroll
        for (int ks = 0; ks < 2; ks++) {
            uint32_t a[4][4], b[8][2];
            #pragma unroll
            for (int mf = 0; mf < 4; mf++)
                ldsm_x4(a[mf], aBase + (mf * 16 * ROW_H + ks * 16) * 2);
            #pragma unroll
            for (int nf = 0; nf < 8; nf++)
                ldsm_x2(b[nf], bBase + (nf * 8 * ROW_H + ks * 16) * 2);
            #pragma unroll
            for (int mf = 0; mf < 4; mf++)
                #pragma unroll
                for (int nf = 0; nf < 8; nf++)
                    mma_f16(c[mf][nf], a[mf], b[nf]);
        }

        if (kt + 2 < NKT) { stage((kt + 2) % 3, kt + 2); CP_COMMIT(); }
    }

    #pragma unroll
    for (int mf = 0; mf < 4; mf++) {
        int row = bm0 + wm + mf * 16 + gid;
        #pragma unroll
        for (int nf = 0; nf < 8; nf++) {
            int col = bn0 + wn + nf * 8 + tig * 2;
            float b0 = bias[col], b1 = bias[col + 1];
            float2 o0 = make_float2(c[mf][nf][0] + b0, c[mf][nf][1] + b1);
            float2 o1 = make_float2(c[mf][nf][2] + b0, c[mf][nf][3] + b1);
            if (SIGMOID) {
                o0.x = 1.f / (1.f + expf(-o0.x)); o0.y = 1.f / (1.f + expf(-o0.y));
                o1.x = 1.f / (1.f + expf(-o1.x)); o1.y = 1.f / (1.f + expf(-o1.y));
            }
            if (HALF_OUT) {
                __half* C = (__half*)Cv;
                *(__half2*)(C + (size_t)row * N + col)       = __floats2half2_rn(o0.x, o0.y);
                *(__half2*)(C + (size_t)(row + 8) * N + col) = __floats2half2_rn(o1.x, o1.y);
            } else {
                float* C = (float*)Cv;
                *(float2*)(C + (size_t)row * N + col) = o0;
                *(float2*)(C + (size_t)(row + 8) * N + col) = o1;
            }
        }
    }
}

#define QKV_TILES 768
#define ALL_TILES (QKV_TILES + 256)

__global__ void __launch_bounds__(128, 2)
mma_gemm_dual(const __half* __restrict__ Aq, const __half* __restrict__ Bq,
              const float* __restrict__ biasq,
              const __half* __restrict__ Ag, const __half* __restrict__ Bg,
              const float* __restrict__ biasg) {
    extern __shared__ char smc[];
    for (int it = blockIdx.x; it < ALL_TILES; it += gridDim.x) {
        __syncthreads();
        if (it < QKV_TILES) {
            int bm = it / 24, bn = it % 24;
            gemm_tile<false, true>(Aq, Bq, biasq, g_qkv_h, 3 * DM, bm * 128, bn * 128, smc);
        } else {
            int t2 = it - QKV_TILES;
            int bm = t2 / 8, bn = t2 % 8;
            gemm_tile<true, true>(Ag, Bg, biasg, g_gate_h, DM, bm * 128, bn * 128, smc);
        }
    }
}

__global__ void __launch_bounds__(128, 2)
mma_gemm_single(const __half* __restrict__ A, const __half* __restrict__ B,
                const float* __restrict__ bias, float* __restrict__ C) {
    extern __shared__ char smc[];
    gemm_tile<false, false>(A, B, bias, C, DM, blockIdx.y * 128, blockIdx.x * 128, smc);
}

// ---------------- weight transpose (single launch) ----------------
__global__ void transpose_all_kernel(const float* __restrict__ wq, const float* __restrict__ wg,
                                     const float* __restrict__ wp) {
    __shared__ float t[32][33];
    int bxg = blockIdx.x;
    const float* W; __half* WT; int N, bx;
    if (bxg < 96)      { W = wq; WT = g_wqkv_h;  N = 3 * DM; bx = bxg * 32; }
    else if (bxg < 128){ W = wg; WT = g_wgate_h; N = DM;     bx = (bxg - 96) * 32; }
    else               { W = wp; WT = g_wproj_h; N = DM;     bx = (bxg - 128) * 32; }
    int by = blockIdx.y * 32;
    int x = threadIdx.x, y = threadIdx.y;
    #pragma unroll
    for (int i = 0; i < 32; i += 8)
        t[y + i][x] = W[(size_t)(by + y + i) * N + bx + x];
    __syncthreads();
    #pragma unroll
    for (int i = 0; i < 32; i += 8)
        WT[(size_t)(bx + y + i) * DM + by + x] = __float2half(t[x][y + i]);
}

// ---------------- LayerNorm ----------------
__global__ void ln_kernel(const float* __restrict__ x, const float* __restrict__ g,
                          const float* __restrict__ bta) {
    __shared__ float red0[8], red1[8];
    int row = blockIdx.x, tid = threadIdx.x;
    const float* xrp = x + (size_t)row * DM;
    float4 xv = *(const float4*)(xrp + tid * 4);
    float s  = xv.x + xv.y + xv.z + xv.w;
    float s2 = xv.x*xv.x + xv.y*xv.y + xv.z*xv.z + xv.w*xv.w;
    #pragma unroll
    for (int o = 16; o > 0; o >>= 1) {
        s  += __shfl_xor_sync(0xffffffffu, s,  o);
        s2 += __shfl_xor_sync(0xffffffffu, s2, o);
    }
    int w = tid >> 5;
    if ((tid & 31) == 0) { red0[w] = s; red1[w] = s2; }
    __syncthreads();
    if (tid < 32) {
        s  = (tid < 8) ? red0[tid] : 0.f;
        s2 = (tid < 8) ? red1[tid] : 0.f;
        #pragma unroll
        for (int o = 4; o > 0; o >>= 1) {
            s  += __shfl_xor_sync(0xffffffffu, s,  o);
            s2 += __shfl_xor_sync(0xffffffffu, s2, o);
        }
        if (tid == 0) { red0[0] = s; red1[0] = s2; }
    }
    __syncthreads();
    float mu   = red0[0] * (1.f / DM);
    float var  = red1[0] * (1.f / DM) - mu * mu;
    float rstd = rsqrtf(var + 1e-5f);
    float4 gv = *(const float4*)(g + tid * 4);
    float4 bv = *(const float4*)(bta + tid * 4);
    __half2* xn2 = (__half2*)(g_xnorm_h + (size_t)row * DM) + tid * 2;
    __half2* xr2 = (__half2*)(g_xr_h    + (size_t)row * DM) + tid * 2;
    xn2[0] = __floats2half2_rn((xv.x - mu) * rstd * gv.x + bv.x,
                               (xv.y - mu) * rstd * gv.y + bv.y);
    xn2[1] = __floats2half2_rn((xv.z - mu) * rstd * gv.z + bv.z,
                               (xv.w - mu) * rstd * gv.w + bv.w);
    xr2[0] = __floats2half2_rn(xv.x, xv.y);
    xr2[1] = __floats2half2_rn(xv.z, xv.w);
}

// ---------------- fused gate-normalize + head split + elu+1 ----------------
__global__ void gatesplit_kernel() {
    __shared__ float red[8];
    int n = blockIdx.x, tid = threadIdx.x;
    const __half2* g2 = (const __half2*)(g_gate_h + (size_t)n * DM);
    float2 g0 = __half22float2(g2[tid * 2]);
    float2 g1 = __half22float2(g2[tid * 2 + 1]);
    float s = g0.x + g0.y + g1.x + g1.y;
    #pragma unroll
    for (int o = 16; o > 0; o >>= 1) s += __shfl_xor_sync(0xffffffffu, s, o);
    if ((tid & 31) == 0) red[tid >> 5] = s;
    __syncthreads();
    if (tid < 32) {
        s = (tid < 8) ? red[tid] : 0.f;
        #pragma unroll
        for (int o = 4; o > 0; o >>= 1) s += __shfl_xor_sync(0xffffffffu, s, o);
        if (tid == 0) red[0] = s;
    }
    __syncthreads();
    float scale = 1.f / (red[0] * (1.f / DM) + 1e-5f);

    int cix = tid * 4;
    int h = cix >> 6, e = cix & 63;
    int b = n >> 11, t = n & 2047;
    const __half2* qkv2 = (const __half2*)(g_qkv_h + (size_t)n * 3072);
    float2 q0 = __half22float2(qkv2[tid * 2]);
    float2 q1 = __half22float2(qkv2[tid * 2 + 1]);
    float2 k0 = __half22float2(qkv2[512 + tid * 2]);
    float2 k1 = __half22float2(qkv2[512 + tid * 2 + 1]);
    float2 v0 = __half22float2(qkv2[1024 + tid * 2]);
    float2 v1 = __half22float2(qkv2[1024 + tid * 2 + 1]);
    float gn0 = g0.x * scale, gn1 = g0.y * scale, gn2 = g1.x * scale, gn3 = g1.y * scale;
    q0.x *= gn0; q0.y *= gn1; q1.x *= gn2; q1.y *= gn3;
    k0.x *= gn0; k0.y *= gn1; k1.x *= gn2; k1.y *= gn3;
    q0.x = (q0.x > 0.f) ? q0.x + 1.f : expf(q0.x);
    q0.y = (q0.y > 0.f) ? q0.y + 1.f : expf(q0.y);
    q1.x = (q1.x > 0.f) ? q1.x + 1.f : expf(q1.x);
    q1.y = (q1.y > 0.f) ? q1.y + 1.f : expf(q1.y);
    k0.x = (k0.x > 0.f) ? k0.x + 1.f : expf(k0.x);
    k0.y = (k0.y > 0.f) ? k0.y + 1.f : expf(k0.y);
    k1.x = (k1.x > 0.f) ? k1.x + 1.f : expf(k1.x);
    k1.y = (k1.y > 0.f) ? k1.y + 1.f : expf(k1.y);
    size_t o = ((size_t)(b * NH + h) * SEQ + t) * DH + e;
    *(__half2*)(g_qh_h + o)     = __floats2half2_rn(q0.x, q0.y);
    *(__half2*)(g_qh_h + o + 2) = __floats2half2_rn(q1.x, q1.y);
    *(__half2*)(g_kh_h + o)     = __floats2half2_rn(k0.x, k0.y);
    *(__half2*)(g_kh_h + o + 2) = __floats2half2_rn(k1.x, k1.y);
    *(__half2*)(g_vh_h + o)     = __floats2half2_rn(v0.x, v0.y);
    *(__half2*)(g_vh_h + o + 2) = __floats2half2_rn(v1.x, v1.y);
}

// ---------------- pass A: per-chunk KV^T (writes [m][d]) + ksum ----------------
__global__ void passA_kernel() {
    __shared__ float ks[64][64];
    __shared__ float vs[64][64];
    int blk = blockIdx.x;
    int bh = blk / NCH, c = blk % NCH;
    const __half* kb = g_kh_h + ((size_t)bh * SEQ + c * CHUNK) * DH;
    const __half* vb = g_vh_h + ((size_t)bh * SEQ + c * CHUNK) * DH;
    int tid = threadIdx.x;
    int d = tid & 63, mg = tid >> 6;
    float acc[16];
    #pragma unroll
    for (int i = 0; i < 16; i++) acc[i] = 0.f;
    float ksum = 0.f;
    for (int half = 0; half < 2; half++) {
        __syncthreads();
        #pragma unroll
        for (int l = 0; l < 4; l++) {
            int id = tid + l * 256;
            int r = id >> 4, c4 = (id & 15) * 4;
            const __half2* ksrc = (const __half2*)(kb + half * 4096 + r * 64 + c4);
            const __half2* vsrc = (const __half2*)(vb + half * 4096 + r * 64 + c4);
            float2 ka = __half22float2(ksrc[0]), kb2 = __half22float2(ksrc[1]);
            float2 va = __half22float2(vsrc[0]), vb2 = __half22float2(vsrc[1]);
            *(float4*)&ks[r][c4] = make_float4(ka.x, ka.y, kb2.x, kb2.y);
            *(float4*)&vs[r][c4] = make_float4(va.x, va.y, vb2.x, vb2.y);
        }
        __syncthreads();
        #pragma unroll 4
        for (int t = 0; t < 64; t++) {
            float kd = ks[t][d];
            if (mg == 0) ksum += kd;
            #pragma unroll
            for (int i = 0; i < 16; i++) acc[i] += kd * vs[t][mg * 16 + i];
        }
    }
    float* kvo = g_kv + (size_t)blk * (DH * DH);
    #pragma unroll
    for (int i = 0; i < 16; i++)
        kvo[(mg * 16 + i) * 64 + d] = acc[i];    // TRANSPOSED [m][d], coalesced over d
    if (mg == 0) g_ksum[blk * DH + d] = ksum;
}

// ---------------- pass B: exclusive prefix over chunks (layout-agnostic) ----------------
__global__ void passB_kernel() {
    int bh = blockIdx.y;
    int e = blockIdx.x * 256 + threadIdx.x;
    float run = 0.f;
    #pragma unroll
    for (int c = 0; c < NCH; c++) {
        size_t idx = ((size_t)bh * NCH + c) * (DH * DH) + e;
        g_kvpre[idx] = run;
        run += g_kv[idx];
    }
    if (blockIdx.x == 0 && threadIdx.x < DH) {
        float r2 = 0.f;
        #pragma unroll
        for (int c = 0; c < NCH; c++) {
            size_t idx = ((size_t)bh * NCH + c) * DH + threadIdx.x;
            g_kspre[idx] = r2;
            r2 += g_ksum[idx];
        }
    }
}

// ---------------- pass C: tensor-core flash-style ----------------
// smem halves layout:
//   q_sm  [128][72]   off 0
//   k_sm  [128][72]   off 9216
//   vt_sm [64][136]   off 18432   (v transposed: [m][s])
//   sp_sm [64][72]    off 27136   (S_pre^T fp16: [m][d])
//   sc_sm [128][136]  off 31744   (masked scores fp16 [t][s])
//   fp32: kp[64], den[128] after 49152 halves
#define PC_Q   0
#define PC_K   (128*72)
#define PC_VT  (PC_K + 128*72)
#define PC_SP  (PC_VT + 64*136)
#define PC_SC  (PC_SP + 64*72)
#define PC_HALVES (PC_SC + 128*136)
#define PC_SMEM (PC_HALVES*2 + (64+128)*4)   // 99072 B

__global__ void __launch_bounds__(128, 2) passC_kernel() {
    extern __shared__ __half smh[];
    __half* q_sm  = smh + PC_Q;
    __half* k_sm  = smh + PC_K;
    __half* vt_sm = smh + PC_VT;
    __half* sp_sm = smh + PC_SP;
    __half* sc_sm = smh + PC_SC;
    float* kp_sm  = (float*)(smh + PC_HALVES);
    float* den_sm = kp_sm + 64;
    uint32_t sbase = smem_u32(smh);

    int blk = blockIdx.x;
    int bh = blk / NCH, c = blk % NCH;
    int b = bh / NH, h = bh % NH;
    int tid = threadIdx.x;
    int wid = tid >> 5, lane = tid & 31;
    int gid = lane >> 2, tig = lane & 3;
    int wm = wid * 32;

    const __half* qb = g_qh_h + ((size_t)bh * SEQ + c * CHUNK) * DH;
    const __half* kb = g_kh_h + ((size_t)bh * SEQ + c * CHUNK) * DH;
    const __half* vb = g_vh_h + ((size_t)bh * SEQ + c * CHUNK) * DH;

    // load q, k (128x64 halves each; rows padded to 72)
    #pragma unroll
    for (int l = 0; l < 8; l++) {
        int id = tid + l * 128;               // 1024: r=id>>3, c8=(id&7)*8
        int r = id >> 3, c8 = (id & 7) * 8;
        *(uint4*)(q_sm + r * 72 + c8) = *(const uint4*)(qb + r * 64 + c8);
        *(uint4*)(k_sm + r * 72 + c8) = *(const uint4*)(kb + r * 64 + c8);
    }
    // v transpose into vt_sm[m][s]
    #pragma unroll
    for (int l = 0; l < 32; l++) {
        int id = tid + l * 128;               // 4096 half2
        int s = id & 127, m2 = id >> 7;
        __half2 v2 = *(const __half2*)(vb + s * 64 + m2 * 2);
        vt_sm[(m2 * 2    ) * 136 + s] = __low2half(v2);
        vt_sm[(m2 * 2 + 1) * 136 + s] = __high2half(v2);
    }
    // S_pre [m][d] fp32 -> fp16
    const float* spg = g_kvpre + (size_t)blk * 4096;
    #pragma unroll
    for (int l = 0; l < 8; l++) {
        int id = tid + l * 128;               // 1024 float4
        int m = id >> 4, d4 = (id & 15) * 4;
        float4 s4 = *(const float4*)(spg + m * 64 + d4);
        __half2* dst = (__half2*)(sp_sm + m * 72 + d4);
        dst[0] = __floats2half2_rn(s4.x, s4.y);
        dst[1] = __floats2half2_rn(s4.z, s4.w);
    }
    if (tid < 64) kp_sm[tid] = g_kspre[(size_t)blk * 64 + tid];
    __syncthreads();

    // Stage 1: scores = q @ k^T  (warp rows [wm, wm+32), all 128 s)
    {
        float c1[2][16][4];
        #pragma unroll
        for (int mf = 0; mf < 2; mf++)
            #pragma unroll
            for (int nf = 0; nf < 16; nf++)
                #pragma unroll
                for (int r = 0; r < 4; r++) c1[mf][nf][r] = 0.f;

        uint32_t aO = sbase + PC_Q * 2 + ((wm + (lane & 15)) * 72 + (lane >> 4) * 8) * 2;
        uint32_t bO = sbase + PC_K * 2 + ((lane & 7) * 72 + ((lane >> 3) & 1) * 8) * 2;
        #pragma unroll
        for (int ks = 0; ks < 4; ks++) {
            uint32_t a[2][4], bfr[16][2];
            #pragma unroll
            for (int mf = 0; mf < 2; mf++)
                ldsm_x4(a[mf], aO + (mf * 16 * 72 + ks * 16) * 2);
            #pragma unroll
            for (int nf = 0; nf < 16; nf++)
                ldsm_x2(bfr[nf], bO + (nf * 8 * 72 + ks * 16) * 2);
            #pragma unroll
            for (int mf = 0; mf < 2; mf++)
                #pragma unroll
                for (int nf = 0; nf < 16; nf++)
                    mma_f16(c1[mf][nf], a[mf], bfr[nf]);
        }
        // masked store to sc_sm
        #pragma unroll
        for (int mf = 0; mf < 2; mf++) {
            int t0 = wm + mf * 16 + gid;
            #pragma unroll
            for (int nf = 0; nf < 16; nf++) {
                int s0 = nf * 8 + tig * 2;
                float v0 = (s0     <= t0) ? c1[mf][nf][0] : 0.f;
                float v1 = (s0 + 1 <= t0) ? c1[mf][nf][1] : 0.f;
                float v2 = (s0     <= t0 + 8) ? c1[mf][nf][2] : 0.f;
                float v3 = (s0 + 1 <= t0 + 8) ? c1[mf][nf][3] : 0.f;
                *(__half2*)(sc_sm + t0 * 136 + s0)       = __floats2half2_rn(v0, v1);
                *(__half2*)(sc_sm + (t0 + 8) * 136 + s0) = __floats2half2_rn(v2, v3);
            }
        }
    }
    __syncthreads();

    // den[t] = sum_s scores + q . kspre
    {
        int t = tid;
        float s = 0.f;
        #pragma unroll 16
        for (int j = 0; j < 128; j += 2) {
            float2 f = __half22float2(*(__half2*)(sc_sm + t * 136 + j));
            s += f.x + f.y;
        }
        #pragma unroll 8
        for (int d = 0; d < 64; d += 2) {
            float2 qf = __half22float2(*(__half2*)(q_sm + t * 72 + d));
            s += qf.x * kp_sm[d] + qf.y * kp_sm[d + 1];
        }
        den_sm[t] = 1.f / (s + 1e-5f);
    }
    __syncthreads();

    // Stage 2: out = scores @ v^T  +  q @ S_pre^T
    float c2[2][8][4];
    #pragma unroll
    for (int mf = 0; mf < 2; mf++)
        #pragma unroll
        for (int nf = 0; nf < 8; nf++)
            #pragma unroll
            for (int r = 0; r < 4; r++) c2[mf][nf][r] = 0.f;

    {
        uint32_t aO = sbase + PC_SC * 2 + ((wm + (lane & 15)) * 136 + (lane >> 4) * 8) * 2;
        uint32_t bO = sbase + PC_VT * 2 + ((lane & 7) * 136 + ((lane >> 3) & 1) * 8) * 2;
        #pragma unroll
        for (int ks = 0; ks < 8; ks++) {
            uint32_t a[2][4], bfr[8][2];
            #pragma unroll
            for (int mf = 0; mf < 2; mf++)
                ldsm_x4(a[mf], aO + (mf * 16 * 136 + ks * 16) * 2);
            #pragma unroll
            for (int nf = 0; nf < 8; nf++)
                ldsm_x2(bfr[nf], bO + (nf * 8 * 136 + ks * 16) * 2);
            #pragma unroll
            for (int mf = 0; mf < 2; mf++)
                #pragma unroll
                for (int nf = 0; nf < 8; nf++)
                    mma_f16(c2[mf][nf], a[mf], bfr[nf]);
        }
    }
    {
        uint32_t aO = sbase + PC_Q * 2 + ((wm + (lane & 15)) * 72 + (lane >> 4) * 8) * 2;
        uint32_t bO = sbase + PC_SP * 2 + ((lane & 7) * 72 + ((lane >> 3) & 1) * 8) * 2;
        #pragma unroll
        for (int ks = 0; ks < 4; ks++) {
            uint32_t a[2][4], bfr[8][2];
            #pragma unroll
            for (int mf = 0; mf < 2; mf++)
                ldsm_x4(a[mf], aO + (mf * 16 * 72 + ks * 16) * 2);
            #pragma unroll
            for (int nf = 0; nf < 8; nf++)
                ldsm_x2(bfr[nf], bO + (nf * 8 * 72 + ks * 16) * 2);
            #pragma unroll
            for (int mf = 0; mf < 2; mf++)
                #pragma unroll
                for (int nf = 0; nf < 8; nf++)
                    mma_f16(c2[mf][nf], a[mf], bfr[nf]);
        }
    }

    // scale by 1/den and write ctx fp16
    #pragma unroll
    for (int mf = 0; mf < 2; mf++) {
        int t0 = wm + mf * 16 + gid;
        int tok0 = b * SEQ + c * CHUNK + t0;
        float i0 = den_sm[t0], i1 = den_sm[t0 + 8];
        #pragma unroll
        for (int nf = 0; nf < 8; nf++) {
            int m0 = nf * 8 + tig * 2;
            *(__half2*)(g_ctx_h + (size_t)tok0 * DM + h * DH + m0) =
                __floats2half2_rn(c2[mf][nf][0] * i0, c2[mf][nf][1] * i0);
            *(__half2*)(g_ctx_h + (size_t)(tok0 + 8) * DM + h * DH + m0) =
                __floats2half2_rn(c2[mf][nf][2] * i1, c2[mf][nf][3] * i1);
        }
    }
}

// ---------------- launch ----------------
extern "C" void kernel_launch(void* const* d_in, const int* in_sizes, int n_in,
                              void* d_out, int out_size) {
    const float* x      = (const float*)d_in[0];
    const float* ln_g   = (const float*)d_in[1];
    const float* ln_b   = (const float*)d_in[2];
    const float* w_qkv  = (const float*)d_in[3];
    const float* b_qkv  = (const float*)d_in[4];
    const float* w_gate = (const float*)d_in[5];
    const float* b_gate = (const float*)d_in[6];
    const float* w_proj = (const float*)d_in[7];
    const float* b_proj = (const float*)d_in[8];
    float* out = (float*)d_out;

    void *p_xnorm, *p_xr, *p_ctx, *p_wqkv, *p_wgate, *p_wproj;
    cudaGetSymbolAddress(&p_xnorm, g_xnorm_h);
    cudaGetSymbolAddress(&p_xr,    g_xr_h);
    cudaGetSymbolAddress(&p_ctx,   g_ctx_h);
    cudaGetSymbolAddress(&p_wqkv,  g_wqkv_h);
    cudaGetSymbolAddress(&p_wgate, g_wgate_h);
    cudaGetSymbolAddress(&p_wproj, g_wproj_h);

    cudaFuncSetAttribute(passC_kernel, cudaFuncAttributeMaxDynamicSharedMemorySize, PC_SMEM);
    cudaFuncSetAttribute(mma_gemm_dual,   cudaFuncAttributeMaxDynamicSharedMemorySize, GEMM_SMEM_BYTES);
    cudaFuncSetAttribute(mma_gemm_single, cudaFuncAttributeMaxDynamicSharedMemorySize, GEMM_SMEM_BYTES);

    // 0. transpose all weights to fp16 [N][K]
    transpose_all_kernel<<<dim3(160, DM / 32), dim3(32, 8)>>>(w_qkv, w_gate, w_proj);
    // 1. LayerNorm
    ln_kernel<<<NTOK, 256>>>(x, ln_g, ln_b);
    // 2+3. persistent dual GEMM
    mma_gemm_dual<<<296, 128, GEMM_SMEM_BYTES>>>(
        (const __half*)p_xnorm, (const __half*)p_wqkv, b_qkv,
        (const __half*)p_xr,    (const __half*)p_wgate, b_gate);
    // 4+5. fused gate-normalize + split + elu+1
    gatesplit_kernel<<<NTOK, 256>>>();
    // 6-8. chunked causal linear attention
    passA_kernel<<<NBH * NCH, 256>>>();
    passB_kernel<<<dim3(16, NBH), 256>>>();
    passC_kernel<<<NBH * NCH, 128, PC_SMEM>>>();
    // 9. projection
    mma_gemm_single<<<dim3(DM / 128, NTOK / 128), 128, GEMM_SMEM_BYTES>>>(
        (const __half*)p_ctx, (const __half*)p_wproj, b_proj, out);
}

// round 15
// speedup vs baseline: 1.6057x; 1.0093x over previous
#include <cuda_runtime.h>
#include <cuda_fp16.h>
#include <math.h>
#include <stdint.h>

// ---------------- problem constants ----------------
#define BATCH 2
#define SEQ   2048
#define DM    1024
#define NH    16
#define DH    64
#define NTOK  (BATCH*SEQ)        // 4096
#define CHUNK 128
#define NCH   (SEQ/CHUNK)        // 16
#define NBH   (BATCH*NH)         // 32

// ---------------- scratch (device globals; no allocs allowed) ----------------
__device__ __half  g_xnorm_h[NTOK*DM];
__device__ __half  g_xr_h   [NTOK*DM];
__device__ __half  g_qkv_h  [NTOK*3*DM];
__device__ __half  g_gate_h [NTOK*DM];
__device__ __half  g_qh_h   [NBH*SEQ*DH];
__device__ __half  g_kh_h   [NBH*SEQ*DH];
__device__ __half  g_vh_h   [NBH*SEQ*DH];
__device__ float   g_kv     [NBH*NCH*DH*DH];   // per chunk: [m][d] (TRANSPOSED)
__device__ float   g_kvpre  [NBH*NCH*DH*DH];   // [m][d]
__device__ float   g_ksum   [NBH*NCH*DH];
__device__ float   g_kspre  [NBH*NCH*DH];
__device__ __half  g_ctx_h  [NTOK*DM];
__device__ __half  g_wqkv_h [(3*DM)*DM];   // [n][k] fp16 (transposed)
__device__ __half  g_wgate_h[DM*DM];       // [n][k]
__device__ __half  g_wproj_h[DM*DM];       // [n][k]

// ---------------- helpers ----------------
__device__ __forceinline__ void mma_f16(float* c, const uint32_t* a, const uint32_t* b) {
    asm volatile(
        "mma.sync.aligned.m16n8k16.row.col.f32.f16.f16.f32 "
        "{%0,%1,%2,%3}, {%4,%5,%6,%7}, {%8,%9}, {%0,%1,%2,%3};"
        : "+f"(c[0]), "+f"(c[1]), "+f"(c[2]), "+f"(c[3])
        : "r"(a[0]), "r"(a[1]), "r"(a[2]), "r"(a[3]), "r"(b[0]), "r"(b[1]));
}
__device__ __forceinline__ void ldsm_x4(uint32_t* r, uint32_t addr) {
    asm volatile("ldmatrix.sync.aligned.m8n8.x4.shared.b16 {%0,%1,%2,%3}, [%4];"
        : "=r"(r[0]), "=r"(r[1]), "=r"(r[2]), "=r"(r[3]) : "r"(addr));
}
__device__ __forceinline__ void ldsm_x2(uint32_t* r, uint32_t addr) {
    asm volatile("ldmatrix.sync.aligned.m8n8.x2.shared.b16 {%0,%1}, [%2];"
        : "=r"(r[0]), "=r"(r[1]) : "r"(addr));
}
__device__ __forceinline__ uint32_t smem_u32(const void* p) {
    uint32_t a;
    asm("{ .reg .u64 t; cvta.to.shared.u64 t, %1; cvt.u32.u64 %0, t; }" : "=r"(a) : "l"(p));
    return a;
}
__device__ __forceinline__ void cp16(uint32_t dst, const void* src) {
    asm volatile("cp.async.cg.shared.global [%0], [%1], 16;" :: "r"(dst), "l"(src));
}
#define CP_COMMIT() asm volatile("cp.async.commit_group;" ::: "memory")
#define CP_WAIT(n)  asm volatile("cp.async.wait_group %0;" :: "n"(n) : "memory")

// ================= fp16 mma.sync GEMM core: BK=64 =================
// CTA tile 128x128, BK=64, 128 threads (4 warps 2x2), warp tile 64x64, 3-stage cp.async.
// Rows padded to 72 halves (144 B) — LDSM conflict-free.
#define ROW_H 72
#define ASTB (128*ROW_H*2)       // 18432 B per stage
#define BSTB (128*ROW_H*2)
#define GEMM_SMEM_BYTES (3*(ASTB+BSTB))  // 110592
#define NKT (DM/64)              // 16 k-tiles

template<bool SIGMOID, bool HALF_OUT>
__device__ __forceinline__ void gemm_tile(
    const __half* __restrict__ A, const __half* __restrict__ B,
    const float* __restrict__ bias, void* __restrict__ Cv,
    int N, int bm0, int bn0, char* sm) {

    uint32_t sA = smem_u32(sm);
    uint32_t sB = sA + 3 * ASTB;
    int tid = threadIdx.x;
    int wid = tid >> 5, lane = tid & 31;
    int gid = lane >> 2, tig = lane & 3;
    int wm = (wid & 1) * 64, wn = (wid >> 1) * 64;

    float c[4][8][4];
    #pragma unroll
    for (int mf = 0; mf < 4; mf++)
        #pragma unroll
        for (int nf = 0; nf < 8; nf++)
            #pragma unroll
            for (int r = 0; r < 4; r++) c[mf][nf][r] = 0.f;

    auto stage = [&](int s, int kt) {
        const __half* Ab = A + (size_t)bm0 * DM + kt * 64;
        const __half* Bb = B + (size_t)bn0 * DM + kt * 64;
        uint32_t sAb = sA + s * ASTB;
        uint32_t sBb = sB + s * BSTB;
        #pragma unroll
        for (int l = 0; l < 8; l++) {
            int id = tid + l * 128;                   // 0..1023
            int r  = id >> 3, ch = id & 7;            // 128 rows x 8 chunks of 8 halves
            cp16(sAb + r * (ROW_H * 2) + ch * 16, Ab + (size_t)r * DM + ch * 8);
            cp16(sBb + r * (ROW_H * 2) + ch * 16, Bb + (size_t)r * DM + ch * 8);
        }
    };

    uint32_t aOff = (uint32_t)(((wm + (lane & 15)) * ROW_H + (lane >> 4) * 8) * 2);
    uint32_t bOff = (uint32_t)(((wn + (lane & 7)) * ROW_H + ((lane >> 3) & 1) * 8) * 2);

    stage(0, 0); CP_COMMIT();
    stage(1, 1); CP_COMMIT();

    for (int kt = 0; kt < NKT; kt++) {
        if (kt + 1 < NKT) { CP_WAIT(1); } else { CP_WAIT(0); }
        __syncthreads();

        int buf = kt % 3;
        uint32_t aBase = sA + buf * ASTB + aOff;
        uint32_t bBase = sB + buf * BSTB + bOff;
        #pragma unroll
        for (int ks = 0; ks < 4; ks++) {
            uint32_t a[4][4], b[8][2];
            #pragma unroll
            for (int mf = 0; mf < 4; mf++)
                ldsm_x4(a[mf], aBase + (mf * 16 * ROW_H + ks * 16) * 2);
            #pragma unroll
            for (int nf = 0; nf < 8; nf++)
                ldsm_x2(b[nf], bBase + (nf * 8 * ROW_H + ks * 16) * 2);
            #pragma unroll
            for (int mf = 0; mf < 4; mf++)
                #pragma unroll
                for (int nf = 0; nf < 8; nf++)
                    mma_f16(c[mf][nf], a[mf], b[nf]);
        }

        if (kt + 2 < NKT) { stage((kt + 2) % 3, kt + 2); CP_COMMIT(); }
    }

    #pragma unroll
    for (int mf = 0; mf < 4; mf++) {
        int row = bm0 + wm + mf * 16 + gid;
        #pragma unroll
        for (int nf = 0; nf < 8; nf++) {
            int col = bn0 + wn + nf * 8 + tig * 2;
            float b0 = bias[col], b1 = bias[col + 1];
            float2 o0 = make_float2(c[mf][nf][0] + b0, c[mf][nf][1] + b1);
            float2 o1 = make_float2(c[mf][nf][2] + b0, c[mf][nf][3] + b1);
            if (SIGMOID) {
                o0.x = 1.f / (1.f + expf(-o0.x)); o0.y = 1.f / (1.f + expf(-o0.y));
                o1.x = 1.f / (1.f + expf(-o1.x)); o1.y = 1.f / (1.f + expf(-o1.y));
            }
            if (HALF_OUT) {
                __half* C = (__half*)Cv;
                *(__half2*)(C + (size_t)row * N + col)       = __floats2half2_rn(o0.x, o0.y);
                *(__half2*)(C + (size_t)(row + 8) * N + col) = __floats2half2_rn(o1.x, o1.y);
            } else {
                float* C = (float*)Cv;
                *(float2*)(C + (size_t)row * N + col) = o0;
                *(float2*)(C + (size_t)(row + 8) * N + col) = o1;
            }
        }
    }
}

#define QKV_TILES 768
#define ALL_TILES (QKV_TILES + 256)

__global__ void __launch_bounds__(128, 2)
mma_gemm_dual(const __half* __restrict__ Aq, const __half* __restrict__ Bq,
              const float* __restrict__ biasq,
              const __half* __restrict__ Ag, const __half* __restrict__ Bg,
              const float* __restrict__ biasg) {
    extern __shared__ char smc[];
    for (int it = blockIdx.x; it < ALL_TILES; it += gridDim.x) {
        __syncthreads();
        if (it < QKV_TILES) {
            int bm = it / 24, bn = it % 24;
            gemm_tile<false, true>(Aq, Bq, biasq, g_qkv_h, 3 * DM, bm * 128, bn * 128, smc);
        } else {
            int t2 = it - QKV_TILES;
            int bm = t2 / 8, bn = t2 % 8;
            gemm_tile<true, true>(Ag, Bg, biasg, g_gate_h, DM, bm * 128, bn * 128, smc);
        }
    }
}

__global__ void __launch_bounds__(128, 2)
mma_gemm_single(const __half* __restrict__ A, const __half* __restrict__ B,
                const float* __restrict__ bias, float* __restrict__ C) {
    extern __shared__ char smc[];
    gemm_tile<false, false>(A, B, bias, C, DM, blockIdx.y * 128, blockIdx.x * 128, smc);
}

// ---------------- prep: LayerNorm rows (blocks 0..4095) + weight transpose (rest) ----------------
__global__ void prep_kernel(const float* __restrict__ x, const float* __restrict__ g,
                            const float* __restrict__ bta,
                            const float* __restrict__ wq, const float* __restrict__ wg,
                            const float* __restrict__ wp) {
    int tid = threadIdx.x;
    if (blockIdx.x < NTOK) {
        __shared__ float red0[8], red1[8];
        int row = blockIdx.x;
        const float* xrp = x + (size_t)row * DM;
        float4 xv = *(const float4*)(xrp + tid * 4);
        float s  = xv.x + xv.y + xv.z + xv.w;
        float s2 = xv.x*xv.x + xv.y*xv.y + xv.z*xv.z + xv.w*xv.w;
        #pragma unroll
        for (int o = 16; o > 0; o >>= 1) {
            s  += __shfl_xor_sync(0xffffffffu, s,  o);
            s2 += __shfl_xor_sync(0xffffffffu, s2, o);
        }
        int w = tid >> 5;
        if ((tid & 31) == 0) { red0[w] = s; red1[w] = s2; }
        __syncthreads();
        if (tid < 32) {
            s  = (tid < 8) ? red0[tid] : 0.f;
            s2 = (tid < 8) ? red1[tid] : 0.f;
            #pragma unroll
            for (int o = 4; o > 0; o >>= 1) {
                s  += __shfl_xor_sync(0xffffffffu, s,  o);
                s2 += __shfl_xor_sync(0xffffffffu, s2, o);
            }
            if (tid == 0) { red0[0] = s; red1[0] = s2; }
        }
        __syncthreads();
        float mu   = red0[0] * (1.f / DM);
        float var  = red1[0] * (1.f / DM) - mu * mu;
        float rstd = rsqrtf(var + 1e-5f);
        float4 gv = *(const float4*)(g + tid * 4);
        float4 bv = *(const float4*)(bta + tid * 4);
        __half2* xn2 = (__half2*)(g_xnorm_h + (size_t)row * DM) + tid * 2;
        __half2* xr2 = (__half2*)(g_xr_h    + (size_t)row * DM) + tid * 2;
        xn2[0] = __floats2half2_rn((xv.x - mu) * rstd * gv.x + bv.x,
                                   (xv.y - mu) * rstd * gv.y + bv.y);
        xn2[1] = __floats2half2_rn((xv.z - mu) * rstd * gv.z + bv.z,
                                   (xv.w - mu) * rstd * gv.w + bv.w);
        xr2[0] = __floats2half2_rn(xv.x, xv.y);
        xr2[1] = __floats2half2_rn(xv.z, xv.w);
    } else {
        __shared__ float t[32][33];
        int idx = blockIdx.x - NTOK;            // 0..5119
        int bxg = idx % 160;
        int by  = (idx / 160) * 32;
        const float* W; __half* WT; int N, bx;
        if (bxg < 96)      { W = wq; WT = g_wqkv_h;  N = 3 * DM; bx = bxg * 32; }
        else if (bxg < 128){ W = wg; WT = g_wgate_h; N = DM;     bx = (bxg - 96) * 32; }
        else               { W = wp; WT = g_wproj_h; N = DM;     bx = (bxg - 128) * 32; }
        int xx = tid & 31, yy = tid >> 5;       // 32 x 8
        #pragma unroll
        for (int i = 0; i < 32; i += 8)
            t[yy + i][xx] = W[(size_t)(by + yy + i) * N + bx + xx];
        __syncthreads();
        #pragma unroll
        for (int i = 0; i < 32; i += 8)
            WT[(size_t)(bx + yy + i) * DM + by + xx] = __float2half(t[xx][yy + i]);
    }
}

// ---------------- fused gate-normalize + head split + elu+1 ----------------
__global__ void gatesplit_kernel() {
    __shared__ float red[8];
    int n = blockIdx.x, tid = threadIdx.x;
    const __half2* g2 = (const __half2*)(g_gate_h + (size_t)n * DM);
    float2 g0 = __half22float2(g2[tid * 2]);
    float2 g1 = __half22float2(g2[tid * 2 + 1]);
    float s = g0.x + g0.y + g1.x + g1.y;
    #pragma unroll
    for (int o = 16; o > 0; o >>= 1) s += __shfl_xor_sync(0xffffffffu, s, o);
    if ((tid & 31) == 0) red[tid >> 5] = s;
    __syncthreads();
    if (tid < 32) {
        s = (tid < 8) ? red[tid] : 0.f;
        #pragma unroll
        for (int o = 4; o > 0; o >>= 1) s += __shfl_xor_sync(0xffffffffu, s, o);
        if (tid == 0) red[0] = s;
    }
    __syncthreads();
    float scale = 1.f / (red[0] * (1.f / DM) + 1e-5f);

    int cix = tid * 4;
    int h = cix >> 6, e = cix & 63;
    int b = n >> 11, t = n & 2047;
    const __half2* qkv2 = (const __half2*)(g_qkv_h + (size_t)n * 3072);
    float2 q0 = __half22float2(qkv2[tid * 2]);
    float2 q1 = __half22float2(qkv2[tid * 2 + 1]);
    float2 k0 = __half22float2(qkv2[512 + tid * 2]);
    float2 k1 = __half22float2(qkv2[512 + tid * 2 + 1]);
    float2 v0 = __half22float2(qkv2[1024 + tid * 2]);
    float2 v1 = __half22float2(qkv2[1024 + tid * 2 + 1]);
    float gn0 = g0.x * scale, gn1 = g0.y * scale, gn2 = g1.x * scale, gn3 = g1.y * scale;
    q0.x *= gn0; q0.y *= gn1; q1.x *= gn2; q1.y *= gn3;
    k0.x *= gn0; k0.y *= gn1; k1.x *= gn2; k1.y *= gn3;
    q0.x = (q0.x > 0.f) ? q0.x + 1.f : expf(q0.x);
    q0.y = (q0.y > 0.f) ? q0.y + 1.f : expf(q0.y);
    q1.x = (q1.x > 0.f) ? q1.x + 1.f : expf(q1.x);
    q1.y = (q1.y > 0.f) ? q1.y + 1.f : expf(q1.y);
    k0.x = (k0.x > 0.f) ? k0.x + 1.f : expf(k0.x);
    k0.y = (k0.y > 0.f) ? k0.y + 1.f : expf(k0.y);
    k1.x = (k1.x > 0.f) ? k1.x + 1.f : expf(k1.x);
    k1.y = (k1.y > 0.f) ? k1.y + 1.f : expf(k1.y);
    size_t o = ((size_t)(b * NH + h) * SEQ + t) * DH + e;
    *(__half2*)(g_qh_h + o)     = __floats2half2_rn(q0.x, q0.y);
    *(__half2*)(g_qh_h + o + 2) = __floats2half2_rn(q1.x, q1.y);
    *(__half2*)(g_kh_h + o)     = __floats2half2_rn(k0.x, k0.y);
    *(__half2*)(g_kh_h + o + 2) = __floats2half2_rn(k1.x, k1.y);
    *(__half2*)(g_vh_h + o)     = __floats2half2_rn(v0.x, v0.y);
    *(__half2*)(g_vh_h + o + 2) = __floats2half2_rn(v1.x, v1.y);
}

// ---------------- pass A: per-chunk KV^T (writes [m][d]) + ksum ----------------
__global__ void passA_kernel() {
    __shared__ float ks[64][64];
    __shared__ float vs[64][64];
    int blk = blockIdx.x;
    int bh = blk / NCH, c = blk % NCH;
    const __half* kb = g_kh_h + ((size_t)bh * SEQ + c * CHUNK) * DH;
    const __half* vb = g_vh_h + ((size_t)bh * SEQ + c * CHUNK) * DH;
    int tid = threadIdx.x;
    int d = tid & 63, mg = tid >> 6;
    float acc[16];
    #pragma unroll
    for (int i = 0; i < 16; i++) acc[i] = 0.f;
    float ksum = 0.f;
    for (int half = 0; half < 2; half++) {
        __syncthreads();
        #pragma unroll
        for (int l = 0; l < 4; l++) {
            int id = tid + l * 256;
            int r = id >> 4, c4 = (id & 15) * 4;
            const __half2* ksrc = (const __half2*)(kb + half * 4096 + r * 64 + c4);
            const __half2* vsrc = (const __half2*)(vb + half * 4096 + r * 64 + c4);
            float2 ka = __half22float2(ksrc[0]), kb2 = __half22float2(ksrc[1]);
            float2 va = __half22float2(vsrc[0]), vb2 = __half22float2(vsrc[1]);
            *(float4*)&ks[r][c4] = make_float4(ka.x, ka.y, kb2.x, kb2.y);
            *(float4*)&vs[r][c4] = make_float4(va.x, va.y, vb2.x, vb2.y);
        }
        __syncthreads();
        #pragma unroll 4
        for (int t = 0; t < 64; t++) {
            float kd = ks[t][d];
            if (mg == 0) ksum += kd;
            #pragma unroll
            for (int i = 0; i < 16; i++) acc[i] += kd * vs[t][mg * 16 + i];
        }
    }
    float* kvo = g_kv + (size_t)blk * (DH * DH);
    #pragma unroll
    for (int i = 0; i < 16; i++)
        kvo[(mg * 16 + i) * 64 + d] = acc[i];
    if (mg == 0) g_ksum[blk * DH + d] = ksum;
}

// ---------------- pass B: exclusive prefix over chunks ----------------
__global__ void passB_kernel() {
    int bh = blockIdx.y;
    int e = blockIdx.x * 256 + threadIdx.x;
    float run = 0.f;
    #pragma unroll
    for (int c = 0; c < NCH; c++) {
        size_t idx = ((size_t)bh * NCH + c) * (DH * DH) + e;
        g_kvpre[idx] = run;
        run += g_kv[idx];
    }
    if (blockIdx.x == 0 && threadIdx.x < DH) {
        float r2 = 0.f;
        #pragma unroll
        for (int c = 0; c < NCH; c++) {
            size_t idx = ((size_t)bh * NCH + c) * DH + threadIdx.x;
            g_kspre[idx] = r2;
            r2 += g_ksum[idx];
        }
    }
}

// ---------------- pass C: tensor-core flash-style ----------------
#define PC_Q   0
#define PC_K   (128*72)
#define PC_VT  (PC_K + 128*72)
#define PC_SP  (PC_VT + 64*136)
#define PC_SC  (PC_SP + 64*72)
#define PC_HALVES (PC_SC + 128*136)
#define PC_SMEM (PC_HALVES*2 + (64+128)*4)   // 99072 B

__global__ void __launch_bounds__(128, 2) passC_kernel() {
    extern __shared__ __half smh[];
    __half* q_sm  = smh + PC_Q;
    __half* k_sm  = smh + PC_K;
    __half* vt_sm = smh + PC_VT;
    __half* sp_sm = smh + PC_SP;
    __half* sc_sm = smh + PC_SC;
    float* kp_sm  = (float*)(smh + PC_HALVES);
    float* den_sm = kp_sm + 64;
    uint32_t sbase = smem_u32(smh);

    int blk = blockIdx.x;
    int bh = blk / NCH, c = blk % NCH;
    int b = bh / NH, h = bh % NH;
    int tid = threadIdx.x;
    int wid = tid >> 5, lane = tid & 31;
    int gid = lane >> 2, tig = lane & 3;
    int wm = wid * 32;

    const __half* qb = g_qh_h + ((size_t)bh * SEQ + c * CHUNK) * DH;
    const __half* kb = g_kh_h + ((size_t)bh * SEQ + c * CHUNK) * DH;
    const __half* vb = g_vh_h + ((size_t)bh * SEQ + c * CHUNK) * DH;

    #pragma unroll
    for (int l = 0; l < 8; l++) {
        int id = tid + l * 128;
        int r = id >> 3, c8 = (id & 7) * 8;
        *(uint4*)(q_sm + r * 72 + c8) = *(const uint4*)(qb + r * 64 + c8);
        *(uint4*)(k_sm + r * 72 + c8) = *(const uint4*)(kb + r * 64 + c8);
    }
    #pragma unroll
    for (int l = 0; l < 32; l++) {
        int id = tid + l * 128;
        int s = id & 127, m2 = id >> 7;
        __half2 v2 = *(const __half2*)(vb + s * 64 + m2 * 2);
        vt_sm[(m2 * 2    ) * 136 + s] = __low2half(v2);
        vt_sm[(m2 * 2 + 1) * 136 + s] = __high2half(v2);
    }
    const float* spg = g_kvpre + (size_t)blk * 4096;
    #pragma unroll
    for (int l = 0; l < 8; l++) {
        int id = tid + l * 128;
        int m = id >> 4, d4 = (id & 15) * 4;
        float4 s4 = *(const float4*)(spg + m * 64 + d4);
        __half2* dst = (__half2*)(sp_sm + m * 72 + d4);
        dst[0] = __floats2half2_rn(s4.x, s4.y);
        dst[1] = __floats2half2_rn(s4.z, s4.w);
    }
    if (tid < 64) kp_sm[tid] = g_kspre[(size_t)blk * 64 + tid];
    __syncthreads();

    {
        float c1[2][16][4];
        #pragma unroll
        for (int mf = 0; mf < 2; mf++)
            #pragma unroll
            for (int nf = 0; nf < 16; nf++)
                #pragma unroll
                for (int r = 0; r < 4; r++) c1[mf][nf][r] = 0.f;

        uint32_t aO = sbase + PC_Q * 2 + ((wm + (lane & 15)) * 72 + (lane >> 4) * 8) * 2;
        uint32_t bO = sbase + PC_K * 2 + ((lane & 7) * 72 + ((lane >> 3) & 1) * 8) * 2;
        #pragma unroll
        for (int ks = 0; ks < 4; ks++) {
            uint32_t a[2][4], bfr[16][2];
            #pragma unroll
            for (int mf = 0; mf < 2; mf++)
                ldsm_x4(a[mf], aO + (mf * 16 * 72 + ks * 16) * 2);
            #pragma unroll
            for (int nf = 0; nf < 16; nf++)
                ldsm_x2(bfr[nf], bO + (nf * 8 * 72 + ks * 16) * 2);
            #pragma unroll
            for (int mf = 0; mf < 2; mf++)
                #pragma unroll
                for (int nf = 0; nf < 16; nf++)
                    mma_f16(c1[mf][nf], a[mf], bfr[nf]);
        }
        #pragma unroll
        for (int mf = 0; mf < 2; mf++) {
            int t0 = wm + mf * 16 + gid;
            #pragma unroll
            for (int nf = 0; nf < 16; nf++) {
                int s0 = nf * 8 + tig * 2;
                float v0 = (s0     <= t0) ? c1[mf][nf][0] : 0.f;
                float v1 = (s0 + 1 <= t0) ? c1[mf][nf][1] : 0.f;
                float v2 = (s0     <= t0 + 8) ? c1[mf][nf][2] : 0.f;
                float v3 = (s0 + 1 <= t0 + 8) ? c1[mf][nf][3] : 0.f;
                *(__half2*)(sc_sm + t0 * 136 + s0)       = __floats2half2_rn(v0, v1);
                *(__half2*)(sc_sm + (t0 + 8) * 136 + s0) = __floats2half2_rn(v2, v3);
            }
        }
    }
    __syncthreads();

    {
        int t = tid;
        float s = 0.f;
        #pragma unroll 16
        for (int j = 0; j < 128; j += 2) {
            float2 f = __half22float2(*(__half2*)(sc_sm + t * 136 + j));
            s += f.x + f.y;
        }
        #pragma unroll 8
        for (int d = 0; d < 64; d += 2) {
            float2 qf = __half22float2(*(__half2*)(q_sm + t * 72 + d));
            s += qf.x * kp_sm[d] + qf.y * kp_sm[d + 1];
        }
        den_sm[t] = 1.f / (s + 1e-5f);
    }
    __syncthreads();

    float c2[2][8][4];
    #pragma unroll
    for (int mf = 0; mf < 2; mf++)
        #pragma unroll
        for (int nf = 0; nf < 8; nf++)
            #pragma unroll
            for (int r = 0; r < 4; r++) c2[mf][nf][r] = 0.f;

    {
        uint32_t aO = sbase + PC_SC * 2 + ((wm + (lane & 15)) * 136 + (lane >> 4) * 8) * 2;
        uint32_t bO = sbase + PC_VT * 2 + ((lane & 7) * 136 + ((lane >> 3) & 1) * 8) * 2;
        #pragma unroll
        for (int ks = 0; ks < 8; ks++) {
            uint32_t a[2][4], bfr[8][2];
            #pragma unroll
            for (int mf = 0; mf < 2; mf++)
                ldsm_x4(a[mf], aO + (mf * 16 * 136 + ks * 16) * 2);
            #pragma unroll
            for (int nf = 0; nf < 8; nf++)
                ldsm_x2(bfr[nf], bO + (nf * 8 * 136 + ks * 16) * 2);
            #pragma unroll
            for (int mf = 0; mf < 2; mf++)
                #pragma unroll
                for (int nf = 0; nf < 8; nf++)
                    mma_f16(c2[mf][nf], a[mf], bfr[nf]);
        }
    }
    {
        uint32_t aO = sbase + PC_Q * 2 + ((wm + (lane & 15)) * 72 + (lane >> 4) * 8) * 2;
        uint32_t bO = sbase + PC_SP * 2 + ((lane & 7) * 72 + ((lane >> 3) & 1) * 8) * 2;
        #pragma unroll
        for (int ks = 0; ks < 4; ks++) {
            uint32_t a[2][4], bfr[8][2];
            #pragma unroll
            for (int mf = 0; mf < 2; mf++)
                ldsm_x4(a[mf], aO + (mf * 16 * 72 + ks * 16) * 2);
            #pragma unroll
            for (int nf = 0; nf < 8; nf++)
                ldsm_x2(bfr[nf], bO + (nf * 8 * 72 + ks * 16) * 2);
            #pragma unroll
            for (int mf = 0; mf < 2; mf++)
                #pragma unroll
                for (int nf = 0; nf < 8; nf++)
                    mma_f16(c2[mf][nf], a[mf], bfr[nf]);
        }
    }

    #pragma unroll
    for (int mf = 0; mf < 2; mf++) {
        int t0 = wm + mf * 16 + gid;
        int tok0 = b * SEQ + c * CHUNK + t0;
        float i0 = den_sm[t0], i1 = den_sm[t0 + 8];
        #pragma unroll
        for (int nf = 0; nf < 8; nf++) {
            int m0 = nf * 8 + tig * 2;
            *(__half2*)(g_ctx_h + (size_t)tok0 * DM + h * DH + m0) =
                __floats2half2_rn(c2[mf][nf][0] * i0, c2[mf][nf][1] * i0);
            *(__half2*)(g_ctx_h + (size_t)(tok0 + 8) * DM + h * DH + m0) =
                __floats2half2_rn(c2[mf][nf][2] * i1, c2[mf][nf][3] * i1);
        }
    }
}

// ---------------- launch ----------------
extern "C" void kernel_launch(void* const* d_in, const int* in_sizes, int n_in,
                              void* d_out, int out_size) {
    const float* x      = (const float*)d_in[0];
    const float* ln_g   = (const float*)d_in[1];
    const float* ln_b   = (const float*)d_in[2];
    const float* w_qkv  = (const float*)d_in[3];
    const float* b_qkv  = (const float*)d_in[4];
    const float* w_gate = (const float*)d_in[5];
    const float* b_gate = (const float*)d_in[6];
    const float* w_proj = (const float*)d_in[7];
    const float* b_proj = (const float*)d_in[8];
    float* out = (float*)d_out;

    void *p_xnorm, *p_xr, *p_ctx, *p_wqkv, *p_wgate, *p_wproj;
    cudaGetSymbolAddress(&p_xnorm, g_xnorm_h);
    cudaGetSymbolAddress(&p_xr,    g_xr_h);
    cudaGetSymbolAddress(&p_ctx,   g_ctx_h);
    cudaGetSymbolAddress(&p_wqkv,  g_wqkv_h);
    cudaGetSymbolAddress(&p_wgate, g_wgate_h);
    cudaGetSymbolAddress(&p_wproj, g_wproj_h);

    cudaFuncSetAttribute(passC_kernel, cudaFuncAttributeMaxDynamicSharedMemorySize, PC_SMEM);
    cudaFuncSetAttribute(mma_gemm_dual,   cudaFuncAttributeMaxDynamicSharedMemorySize, GEMM_SMEM_BYTES);
    cudaFuncSetAttribute(mma_gemm_single, cudaFuncAttributeMaxDynamicSharedMemorySize, GEMM_SMEM_BYTES);

    // 0+1. prep: LayerNorm + weight transpose in one launch
    prep_kernel<<<NTOK + 160 * 32, 256>>>(x, ln_g, ln_b, w_qkv, w_gate, w_proj);
    // 2+3. persistent dual GEMM (BK=64)
    mma_gemm_dual<<<296, 128, GEMM_SMEM_BYTES>>>(
        (const __half*)p_xnorm, (const __half*)p_wqkv, b_qkv,
        (const __half*)p_xr,    (const __half*)p_wgate, b_gate);
    // 4+5. fused gate-normalize + split + elu+1
    gatesplit_kernel<<<NTOK, 256>>>();
    // 6-8. chunked causal linear attention
    passA_kernel<<<NBH * NCH, 256>>>();
    passB_kernel<<<dim3(16, NBH), 256>>>();
    passC_kernel<<<NBH * NCH, 128, PC_SMEM>>>();
    // 9. projection (BK=64)
    mma_gemm_single<<<dim3(DM / 128, NTOK / 128), 128, GEMM_SMEM_BYTES>>>(
        (const __half*)p_ctx, (const __half*)p_wproj, b_proj, out);
}